// round 16
// baseline (speedup 1.0000x reference)
#include <cuda_runtime.h>
#include <cuda_bf16.h>
#include <cstdint>

// ============================================================================
// Chain is linear/separable: Y = M_H(47x64) · X · M_W^T(64x30) per plane.
// Rank-16 W-split, small dim kept longest:
//   A:  T1 = X · V_W^T      (64x16, red 64)   X read DIRECT from global
//   B': T2 = M_H · T1       (47x16, red 64)
//   C': Y  = T2 · U_W^T     (47x30, red 16)
// 136K FMA/plane. R12 profile: occ 23.9% (2 CTAs/SM via 102 regs + 105KB smem),
// issue 33.8% -> latency-bound. This round: no X staging, 2 planes/block,
// 36.6KB static smem, launch_bounds(256,4) -> 4 CTAs/SM, 50% occ.
// ============================================================================

#define FFMA2(d,a,b,c) asm("fma.rn.f32x2 %0, %1, %2, %3;" : "=l"(d) : "l"(a),"l"(b),"l"(c))
#define PACKDUP(d,v)   asm("mov.b64 %0, {%1, %1};" : "=l"(d) : "f"(v))
#define UNPACK2(lo,hi,v) asm("mov.b64 {%0, %1}, %2;" : "=f"(lo),"=f"(hi) : "l"(v))
typedef unsigned long long ull;

struct ResOp { int out, mode, align; float r; };

__constant__ ResOp H_OPS[23] = {
    {16,0,0,(float)(64.0/16.0)},  {32,0,0,(float)(16.0/32.0)},
    {20,0,0,(float)(32.0/20.0)},  {80,0,0,(float)(20.0/80.0)},
    {16,0,0,(float)(80.0/16.0)},  {32,0,0,(float)(16.0/32.0)},
    {16,1,0,(float)(32.0/16.0)},  {32,1,0,(float)(16.0/32.0)},
    {20,1,0,(float)(32.0/20.0)},  {80,1,0,(float)(20.0/80.0)},
    {16,1,1,(float)(79.0/15.0)},  {32,1,1,(float)(15.0/31.0)},
    {16,2,0,(float)(32.0/16.0)},  {32,2,0,(float)(16.0/32.0)},
    {20,2,0,(float)(32.0/20.0)},  {80,2,0,(float)(20.0/80.0)},
    {16,2,1,(float)(79.0/15.0)},  {32,2,1,(float)(15.0/31.0)},
    {54,0,0,(float)(32.0/54.0)},  {108,1,0,(float)(54.0/108.0)},
    {54,1,1,(float)(107.0/53.0)}, {43,2,0,(float)(54.0/43.0)},
    {47,2,1,(float)(42.0/46.0)},
};
__constant__ ResOp W_OPS[23] = {
    {16,0,0,(float)(64.0/16.0)},  {32,0,0,(float)(16.0/32.0)},
    {20,0,0,(float)(32.0/20.0)},  {80,0,0,(float)(20.0/80.0)},
    {24,0,0,(float)(80.0/24.0)},  {72,0,0,(float)(24.0/72.0)},
    {16,1,0,(float)(72.0/16.0)},  {32,1,0,(float)(16.0/32.0)},
    {20,1,0,(float)(32.0/20.0)},  {80,1,0,(float)(20.0/80.0)},
    {24,1,1,(float)(79.0/23.0)},  {72,1,1,(float)(23.0/71.0)},
    {16,2,0,(float)(72.0/16.0)},  {32,2,0,(float)(16.0/32.0)},
    {20,2,0,(float)(32.0/20.0)},  {80,2,0,(float)(20.0/80.0)},
    {24,2,1,(float)(79.0/23.0)},  {72,2,1,(float)(23.0/71.0)},
    {144,0,0,(float)(72.0/144.0)},{172,1,0,(float)(144.0/172.0)},
    {68,1,1,(float)(171.0/67.0)}, {61,2,0,(float)(68.0/61.0)},
    {30,2,1,(float)(60.0/29.0)},
};

// g_MHt[h*48+i] = M_H[i][h] (transposed; col i=47 zero)
// g_VW [c*68+w] = V_W[c][w]
// g_UWT[c*32+j] = U_W[j][c] (j>=30 zero)
__device__ __align__(16) float g_MHt[64*48];
__device__ __align__(16) float g_VW [16*68];
__device__ __align__(16) float g_UWT[16*32];

__device__ __forceinline__ float cc1(float t){ return ((1.25f*t - 2.25f)*t)*t + 1.0f; }
__device__ __forceinline__ float cc2(float t){ return (((-0.75f)*t + 3.75f)*t - 6.0f)*t + 3.0f; }
__device__ __forceinline__ int clampi(int v,int lo,int hi){ return v<lo?lo:(v>hi?hi:v); }

__global__ void build_mats() {
    const int bid = blockIdx.x;
    int kind, start, count, insz, col;
    if (bid < 64)       { kind=0; start=0;  count=23; insz=64; col=bid; }
    else if (bid < 128) { kind=1; start=0;  count=13; insz=64; col=bid-64; }
    else                { kind=2; start=13; count=10; insz=16; col=bid-128; }

    __shared__ float bufA[172], bufB[172];
    float* bufs[2] = {bufA, bufB};
    const int t = threadIdx.x;
    if (t < insz) bufA[t] = (t == col) ? 1.0f : 0.0f;
    __syncthreads();

    int cur = 0, in = insz;
    for (int o = start; o < start+count; o++) {
        ResOp op = (kind==0) ? H_OPS[o] : W_OPS[o];
        const float* src = bufs[cur];
        float* dst = bufs[cur^1];
        if (t < op.out) {
            float d = (float)t, v;
            if (op.mode == 0) {
                int id = (int)floorf(__fmul_rn(d, op.r));
                if (id > in-1) id = in-1;
                v = src[id];
            } else {
                float s;
                if (op.align) s = __fmul_rn(d, op.r);
                else {
                    s = __fadd_rn(__fmul_rn(__fadd_rn(d, 0.5f), op.r), -0.5f);
                    if (op.mode == 1) s = fmaxf(s, 0.0f);
                }
                float x0 = floorf(s);
                int i0 = (int)x0;
                float tt = __fadd_rn(s, -x0);
                if (op.mode == 1) {
                    int i1 = i0+1; if (i1 > in-1) i1 = in-1;
                    v = (1.0f-tt)*src[i0] + tt*src[i1];
                } else {
                    float w0=cc2(tt+1.0f), w1=cc1(tt), w2=cc1(1.0f-tt), w3=cc2(2.0f-tt);
                    v = w0*src[clampi(i0-1,0,in-1)] + w1*src[clampi(i0,0,in-1)]
                      + w2*src[clampi(i0+1,0,in-1)] + w3*src[clampi(i0+2,0,in-1)];
                }
            }
            dst[t] = v;
        }
        __syncthreads();
        cur ^= 1; in = op.out;
    }

    const float* fin = bufs[cur];
    if (kind == 0) {
        if (t < 48) g_MHt[col*48 + t] = (t < 47) ? fin[t] : 0.0f;
    } else if (kind == 1) {
        if (t < 16) g_VW[t*68 + col] = fin[t];
    } else {
        if (t < 32) g_UWT[col*32 + t] = (t < 30) ? fin[t] : 0.0f;
    }
}

// ----------------------------------------------------------------------------
// Main: 4096 blocks x 256 threads, 2 planes/block, 4 warps/plane.
// Static smem: T1s[2][64][20]=2560, VWs 1088, UWTs 512, MHs 3072,
// T2s[2][48][20]=1920 -> 9152 floats = 36.6KB -> 4 CTAs/SM (regs capped 64).
// Warp w: plane p=w>>2, quarter q4=w&3. lane: l8=lane&7, l4=lane>>3.
// Stage A: h = q4*16 + l8 + 8k (k<2); X read from GLOBAL (16B, 4-way bcast).
// Stage B'/C': i = q4*12 + l8 + 8k (k<2; k=1 valid only l8<4; i=47 pad).
// ----------------------------------------------------------------------------
__global__ __launch_bounds__(256, 4) void resize_main(const float* __restrict__ x,
                                                      float* __restrict__ out) {
    __shared__ __align__(16) float T1s[2*64*20];
    __shared__ __align__(16) float VWs[16*68];
    __shared__ __align__(16) float UWTs[16*32];
    __shared__ __align__(16) float MHs[64*48];
    __shared__ __align__(16) float T2s[2*48*20];

    const int t = threadIdx.x;

    for (int k = t; k < 1088; k += 256) VWs[k]  = g_VW[k];
    for (int k = t; k < 512;  k += 256) UWTs[k] = g_UWT[k];
    for (int k = t; k < 3072; k += 256) MHs[k]  = g_MHt[k];
    __syncthreads();

    const int lane = t & 31, w = t >> 5;
    const int p = w >> 2, q4 = w & 3;
    const int l8 = lane & 7, l4 = lane >> 3;

    // ---- Stage A: T1[h][c] = sum_w X[h][w] * V_W[c][w] ----
    // 2h x 4c tile; X straight from global (LDG.128, 8 distinct addrs, 4-way bcast).
    {
        ull accA[2][4];
#pragma unroll
        for (int k = 0; k < 2; k++)
#pragma unroll
            for (int cj = 0; cj < 4; cj++) accA[k][cj] = 0ull;
        const float* Xg = x + ((size_t)blockIdx.x*2 + p)*4096 + (q4*16 + l8)*64;
#pragma unroll 4
        for (int wq = 0; wq < 16; wq++) {
            ulonglong2 vw[4];
#pragma unroll
            for (int cj = 0; cj < 4; cj++)
                vw[cj] = *(const ulonglong2*)&VWs[(l4 + 4*cj)*68 + wq*4];
#pragma unroll
            for (int k = 0; k < 2; k++) {
                ulonglong2 xvv = *(const ulonglong2*)&Xg[k*512 + wq*4];  // +8 rows = 512 floats
#pragma unroll
                for (int cj = 0; cj < 4; cj++) {
                    FFMA2(accA[k][cj], xvv.x, vw[cj].x, accA[k][cj]);
                    FFMA2(accA[k][cj], xvv.y, vw[cj].y, accA[k][cj]);
                }
            }
        }
#pragma unroll
        for (int k = 0; k < 2; k++)
#pragma unroll
            for (int cj = 0; cj < 4; cj++) {
                float lo, hi; UNPACK2(lo, hi, accA[k][cj]);
                // word = h*20 + c : (20*l8 + l4) mod 32 all-distinct -> conflict-free
                T1s[p*1280 + (q4*16 + l8 + 8*k)*20 + (l4 + 4*cj)] = lo + hi;
            }
    }
    __syncthreads();

    const int ibase = q4*12 + l8;                      // k=0 row, <=43
    const int i1c   = (l8 < 4) ? ibase + 8 : ibase;    // k=1 row (clamped for invalid lanes)

    // ---- Stage B': T2[i][c] = sum_h M_H[i][h] * T1[h][c] ----
    // 2i x 4c tile (c = 4*l4+cj); h loop-uniform -> T1 float4 is 4-addr bcast.
    {
        float accB[2][4];
#pragma unroll
        for (int k = 0; k < 2; k++)
#pragma unroll
            for (int cj = 0; cj < 4; cj++) accB[k][cj] = 0.0f;
        const float* T1p = T1s + p*1280;
#pragma unroll 4
        for (int h = 0; h < 64; h++) {
            float4 t1v = *(const float4*)&T1p[h*20 + 4*l4];
            float m0 = MHs[h*48 + ibase];
            float m1 = MHs[h*48 + i1c];
            accB[0][0] = __fmaf_rn(m0, t1v.x, accB[0][0]);
            accB[0][1] = __fmaf_rn(m0, t1v.y, accB[0][1]);
            accB[0][2] = __fmaf_rn(m0, t1v.z, accB[0][2]);
            accB[0][3] = __fmaf_rn(m0, t1v.w, accB[0][3]);
            accB[1][0] = __fmaf_rn(m1, t1v.x, accB[1][0]);
            accB[1][1] = __fmaf_rn(m1, t1v.y, accB[1][1]);
            accB[1][2] = __fmaf_rn(m1, t1v.z, accB[1][2]);
            accB[1][3] = __fmaf_rn(m1, t1v.w, accB[1][3]);
        }
        float* T2p = T2s + p*960;
        *(float4*)&T2p[ibase*20 + 4*l4] =
            make_float4(accB[0][0], accB[0][1], accB[0][2], accB[0][3]);
        if (l8 < 4)   // rows 8..11 of this warp's 12-row strip (i<=47 pad row OK)
            *(float4*)&T2p[(ibase + 8)*20 + 4*l4] =
                make_float4(accB[1][0], accB[1][1], accB[1][2], accB[1][3]);
    }
    __syncthreads();

    // ---- Stage C': Y[i][j] = sum_c T2[i][c] * U_W[j][c] ----
    // 2i x 4 j-pairs (jp = 4*l4+q).
    {
        ull accC[2][4];
#pragma unroll
        for (int k = 0; k < 2; k++)
#pragma unroll
            for (int q = 0; q < 4; q++) accC[k][q] = 0ull;
        const float* T2p = T2s + p*960;
#pragma unroll 4
        for (int c = 0; c < 16; c++) {
            ulonglong2 uw0 = *(const ulonglong2*)&UWTs[c*32 + l4*8];
            ulonglong2 uw1 = *(const ulonglong2*)&UWTs[c*32 + l4*8 + 4];
            float td0 = T2p[ibase*20 + c];
            float td1 = T2p[i1c*20 + c];
            ull d0, d1; PACKDUP(d0, td0); PACKDUP(d1, td1);
            FFMA2(accC[0][0], d0, uw0.x, accC[0][0]);
            FFMA2(accC[0][1], d0, uw0.y, accC[0][1]);
            FFMA2(accC[0][2], d0, uw1.x, accC[0][2]);
            FFMA2(accC[0][3], d0, uw1.y, accC[0][3]);
            FFMA2(accC[1][0], d1, uw0.x, accC[1][0]);
            FFMA2(accC[1][1], d1, uw0.y, accC[1][1]);
            FFMA2(accC[1][2], d1, uw1.x, accC[1][2]);
            FFMA2(accC[1][3], d1, uw1.y, accC[1][3]);
        }
        float* O = out + ((size_t)blockIdx.x*2 + p)*1410;
#pragma unroll
        for (int q = 0; q < 4; q++) {          // k=0: i = ibase <= 43 always valid
            int jp = 4*l4 + q;
            if (jp < 15) {
                float lo, hi; UNPACK2(lo, hi, accC[0][q]);
                *(float2*)&O[ibase*30 + 2*jp] = make_float2(lo, hi);
            }
        }
        if (l8 < 4) {                          // k=1: i = ibase+8, skip pad i=47
            int i1 = ibase + 8;
            if (i1 < 47) {
#pragma unroll
                for (int q = 0; q < 4; q++) {
                    int jp = 4*l4 + q;
                    if (jp < 15) {
                        float lo, hi; UNPACK2(lo, hi, accC[1][q]);
                        *(float2*)&O[i1*30 + 2*jp] = make_float2(lo, hi);
                    }
                }
            }
        }
    }
}

extern "C" void kernel_launch(void* const* d_in, const int* in_sizes, int n_in,
                              void* d_out, int out_size) {
    const float* x = (const float*)d_in[0];
    float* out = (float*)d_out;
    (void)in_sizes; (void)n_in; (void)out_size;

    build_mats<<<144, 192>>>();
    resize_main<<<4096, 256>>>(x, out);
}